// round 10
// baseline (speedup 1.0000x reference)
#include <cuda_runtime.h>
#include <cstdint>

// HashGrid3D: 16-level Instant-NGP style hash grid encode.
// xyt: (1048576, 3) fp32 in [0,1); tables: (16, 524288, 2) fp32.
// out: (1048576, 32) fp32.
//
// hash(c) = (cx*1 ^ cy*2654435761 ^ cz*805459861) & (T-1), T = 2^19.
//
// R10: main kernel untouched (R9 config: zero smem -> full 228KB L1,
// dense gmem levels 0-8, hashed 9-15). Two pipeline-level changes:
//  - build_dense forked onto a second stream, overlapping the sort chain
//    (independent data; rejoin before the main kernel)
//  - Morton-ordered buckets: CTA's 1024 consecutive sorted points form a
//    compact 3D block instead of a thin slab -> smaller per-CTA hot set,
//    better cross-warp L1 reuse at high dense levels.

#define T_SIZE 524288u
#define HMASK  (T_SIZE - 1u)
#define PY     2654435761u
#define PZ     805459861u

#define NPTS 1048576

// dense levels 0..8: N = 16,20,25,32,40,51,64,81,102
#define DENSE_TOTAL 2111933
__device__ float4 g_dense[DENSE_TOTAL];   // 33.8 MB scratch

#define DOFF0 0
#define DOFF1 4096
#define DOFF2 12096
#define DOFF3 27721
#define DOFF4 60489
#define DOFF5 124489
#define DOFF6 257140
#define DOFF7 519284
#define DOFF8 1050725

// build: one thread per x-PAIR of entries, pairs/level = ceil(N/2)*N*N
#define BPAIRS_TOTAL 1060860
#define BPA 0
#define BPB 2048
#define BPC 6048
#define BPD 14173
#define BPE 30557
#define BPF 62557
#define BPG 130183
#define BPH 261255
#define BPI 530256

// ---- spatial binning scratch ----
#define NBDIM 32
#define NBUCKETS (NBDIM * NBDIM * NBDIM)   // 32768
__device__ uint32_t g_count[NBUCKETS];     // counts -> exclusive bases (scan)
__device__ uint32_t g_rank[NPTS];          // per-point rank within bucket
__device__ float4   g_perm[NPTS];          // (x,y,z, bit-cast orig idx)

struct Corners { float2 g[8]; };

__device__ __forceinline__ void trilerp(
    const Corners& c, float tx, float ty, float tz, float& r0, float& r1)
{
    const float ux = 1.0f - tx, uy = 1.0f - ty, uz = 1.0f - tz;
    const float wy0z0 = uy * uz, wy1z0 = ty * uz;
    const float wy0z1 = uy * tz, wy1z1 = ty * tz;
    const float w000 = ux * wy0z0, w100 = tx * wy0z0;
    const float w010 = ux * wy1z0, w110 = tx * wy1z0;
    const float w001 = ux * wy0z1, w101 = tx * wy0z1;
    const float w011 = ux * wy1z1, w111 = tx * wy1z1;

    float a = w000 * c.g[0].x;
    float b = w000 * c.g[0].y;
    a = fmaf(w100, c.g[1].x, a);  b = fmaf(w100, c.g[1].y, b);
    a = fmaf(w010, c.g[2].x, a);  b = fmaf(w010, c.g[2].y, b);
    a = fmaf(w110, c.g[3].x, a);  b = fmaf(w110, c.g[3].y, b);
    a = fmaf(w001, c.g[4].x, a);  b = fmaf(w001, c.g[4].y, b);
    a = fmaf(w101, c.g[5].x, a);  b = fmaf(w101, c.g[5].y, b);
    a = fmaf(w011, c.g[6].x, a);  b = fmaf(w011, c.g[6].y, b);
    a = fmaf(w111, c.g[7].x, a);  b = fmaf(w111, c.g[7].y, b);
    r0 = a; r1 = b;
}

__device__ __forceinline__ void corner_setup(
    int N, float x, float y, float z,
    int& ix, int& iy, int& iz, int& ix1, int& iy1, int& iz1,
    float& tx, float& ty, float& tz)
{
    const float fN = (float)N;
    float sx = x * fN, sy = y * fN, sz = z * fN;
    float fx = floorf(sx), fy = floorf(sy), fz = floorf(sz);
    tx = sx - fx; ty = sy - fy; tz = sz - fz;
    ix = (int)fx; iy = (int)fy; iz = (int)fz;
    if (ix >= N) ix -= N;
    if (iy >= N) iy -= N;
    if (iz >= N) iz -= N;
    ix1 = ix + 1; if (ix1 >= N) ix1 -= N;
    iy1 = iy + 1; if (iy1 >= N) iy1 -= N;
    iz1 = iz + 1; if (iz1 >= N) iz1 -= N;
}

// hashed LDG level with x-parity LDG.128 merging (levels 9..15)
__device__ __forceinline__ void level_ldg(
    const float2* __restrict__ tbl, int N,
    float x, float y, float z, float& r0, float& r1)
{
    int ix, iy, iz, ix1, iy1, iz1;
    float tx, ty, tz;
    corner_setup(N, x, y, z, ix, iy, iz, ix1, iy1, iz1, tx, ty, tz);

    const uint32_t hy0 = (uint32_t)iy  * PY, hy1 = (uint32_t)iy1 * PY;
    const uint32_t hz0 = (uint32_t)iz  * PZ, hz1 = (uint32_t)iz1 * PZ;
    const uint32_t ux0 = (uint32_t)ix,  ux1 = (uint32_t)ix1;
    uint32_t s[4];
    s[0] = hy0 ^ hz0; s[1] = hy1 ^ hz0; s[2] = hy0 ^ hz1; s[3] = hy1 ^ hz1;

    Corners c;
    const bool pair = ((ix & 1) == 0) && (ix1 == ix + 1);
    if (pair) {
        const float4* __restrict__ tbl4 = (const float4*)tbl;
#pragma unroll
        for (int k = 0; k < 4; ++k) {
            uint32_t h0 = (ux0 ^ s[k]) & HMASK;          // h1 = h0 ^ 1
            float4 q = __ldg(tbl4 + (h0 >> 1));
            if (h0 & 1) { c.g[2*k] = make_float2(q.z, q.w); c.g[2*k+1] = make_float2(q.x, q.y); }
            else        { c.g[2*k] = make_float2(q.x, q.y); c.g[2*k+1] = make_float2(q.z, q.w); }
        }
    } else {
#pragma unroll
        for (int k = 0; k < 4; ++k) {
            uint32_t h0 = (ux0 ^ s[k]) & HMASK;
            uint32_t h1 = (ux1 ^ s[k]) & HMASK;
            c.g[2*k]   = __ldg(tbl + h0);
            c.g[2*k+1] = __ldg(tbl + h1);
        }
    }
    trilerp(c, tx, ty, tz, r0, r1);
}

// dense gmem level: x-pair + x-wrap baked into float4 entries (levels 0..8)
__device__ __forceinline__ void level_dense(
    const float4* __restrict__ t4, int N,
    float x, float y, float z, float& r0, float& r1)
{
    int ix, iy, iz, ix1, iy1, iz1;
    float tx, ty, tz;
    corner_setup(N, x, y, z, ix, iy, iz, ix1, iy1, iz1, tx, ty, tz);

    const int NN = N * N;
    const float4 q00 = __ldg(t4 + iz  * NN + iy  * N + ix);
    const float4 q10 = __ldg(t4 + iz  * NN + iy1 * N + ix);
    const float4 q01 = __ldg(t4 + iz1 * NN + iy  * N + ix);
    const float4 q11 = __ldg(t4 + iz1 * NN + iy1 * N + ix);

    Corners c;
    c.g[0] = make_float2(q00.x, q00.y); c.g[1] = make_float2(q00.z, q00.w);
    c.g[2] = make_float2(q10.x, q10.y); c.g[3] = make_float2(q10.z, q10.w);
    c.g[4] = make_float2(q01.x, q01.y); c.g[5] = make_float2(q01.z, q01.w);
    c.g[6] = make_float2(q11.x, q11.y); c.g[7] = make_float2(q11.z, q11.w);
    trilerp(c, tx, ty, tz, r0, r1);
}

// ---- binning pipeline ----

// spread 5 bits to every 3rd position (for 15-bit Morton)
__device__ __forceinline__ uint32_t spread5(uint32_t x)
{
    x &= 0x1Fu;
    x = (x | (x << 8)) & 0x100Fu;
    x = (x | (x << 4)) & 0x10C3u;
    x = (x | (x << 2)) & 0x1249u;
    return x;
}

__device__ __forceinline__ int bucket_of(float x, float y, float z)
{
    int bx = (int)(x * (float)NBDIM); if (bx > NBDIM - 1) bx = NBDIM - 1;
    int by = (int)(y * (float)NBDIM); if (by > NBDIM - 1) by = NBDIM - 1;
    int bz = (int)(z * (float)NBDIM); if (bz > NBDIM - 1) bz = NBDIM - 1;
    // Morton order: consecutive buckets form compact 3D blocks
    return (int)(spread5((uint32_t)bx) | (spread5((uint32_t)by) << 1)
                 | (spread5((uint32_t)bz) << 2));
}

__global__ void __launch_bounds__(256) zero_kernel()
{
    const int i = blockIdx.x * blockDim.x + threadIdx.x;
    if (i < NBUCKETS) g_count[i] = 0;
}

__global__ void __launch_bounds__(256) hist_kernel(const float* __restrict__ xyt, int n)
{
    const int p = blockIdx.x * blockDim.x + threadIdx.x;
    if (p >= n) return;
    const float x = xyt[3 * p + 0];
    const float y = xyt[3 * p + 1];
    const float z = xyt[3 * p + 2];
    g_rank[p] = atomicAdd(&g_count[bucket_of(x, y, z)], 1u);
}

// single-block exclusive scan of g_count (32768 = 1024 threads x 32), in place
__global__ void __launch_bounds__(1024) scan_kernel()
{
    __shared__ uint32_t tsum[1024];
    const int t = threadIdx.x;
    const int base = t * 32;
    uint32_t vals[32];
    uint32_t s = 0;
#pragma unroll
    for (int j = 0; j < 32; ++j) { vals[j] = g_count[base + j]; s += vals[j]; }
    tsum[t] = s;
    __syncthreads();
    for (int off = 1; off < 1024; off <<= 1) {
        uint32_t v = (t >= off) ? tsum[t - off] : 0u;
        __syncthreads();
        tsum[t] += v;
        __syncthreads();
    }
    uint32_t run = (t == 0) ? 0u : tsum[t - 1];   // exclusive prefix
#pragma unroll
    for (int j = 0; j < 32; ++j) { uint32_t c = vals[j]; g_count[base + j] = run; run += c; }
}

// atomic-free scatter: slot = base[bucket] + rank[p]
__global__ void __launch_bounds__(256) scatter_kernel(const float* __restrict__ xyt, int n)
{
    const int p = blockIdx.x * blockDim.x + threadIdx.x;
    if (p >= n) return;
    const float x = xyt[3 * p + 0];
    const float y = xyt[3 * p + 1];
    const float z = xyt[3 * p + 2];
    const uint32_t slot = g_count[bucket_of(x, y, z)] + g_rank[p];
    g_perm[slot] = make_float4(x, y, z, __int_as_float(p));
}

// ---- pre-kernel: materialize dense x-paired tables for levels 0..8 ----
__global__ void __launch_bounds__(256) build_dense_kernel(
    const float2* __restrict__ tables)
{
    const int i = blockIdx.x * blockDim.x + threadIdx.x;
    if (i >= BPAIRS_TOTAL) return;

    const int POFF[9]  = {BPA, BPB, BPC, BPD, BPE, BPF, BPG, BPH, BPI};
    const int DOFF[9]  = {DOFF0, DOFF1, DOFF2, DOFF3, DOFF4, DOFF5, DOFF6, DOFF7, DOFF8};
    const int DN[9]    = {16, 20, 25, 32, 40, 51, 64, 81, 102};

    int l = 0;
#pragma unroll
    for (int k = 1; k < 9; ++k) if (i >= POFF[k]) l = k;

    const int N = DN[l];
    const int hw = (N + 1) >> 1;        // pairs per row
    const int local = i - POFF[l];
    const int pi = local % hw;
    const int r  = local / hw;
    const int iy = r % N;
    const int iz = r / N;
    const int ix = 2 * pi;

    const float2* __restrict__ tbl  = tables + (size_t)l * T_SIZE;
    const float4* __restrict__ tbl4 = (const float4*)tbl;
    const uint32_t s = ((uint32_t)iy * PY) ^ ((uint32_t)iz * PZ);

    const uint32_t h0 = ((uint32_t)ix ^ s) & HMASK;
    const float4 q = __ldg(tbl4 + (h0 >> 1));
    float2 ga, gb;   // g(ix), g(ix+1)
    if (h0 & 1) { ga = make_float2(q.z, q.w); gb = make_float2(q.x, q.y); }
    else        { ga = make_float2(q.x, q.y); gb = make_float2(q.z, q.w); }

    const int x2 = (ix + 2 < N) ? ix + 2 : ix + 2 - N;
    const float2 gc = __ldg(tbl + (((uint32_t)x2 ^ s) & HMASK));

    float4* dst = g_dense + DOFF[l] + (size_t)(iz * N + iy) * N + ix;
    if (ix + 1 < N) {
        dst[0] = make_float4(ga.x, ga.y, gb.x, gb.y);
        dst[1] = make_float4(gb.x, gb.y, gc.x, gc.y);
    } else {
        // even N never hits this; odd N last lone entry: (g(N-1), g(0))
        const float2 g0 = __ldg(tbl + (s & HMASK));     // x=0 -> h = s
        dst[0] = make_float4(ga.x, ga.y, g0.x, g0.y);
    }
}

__global__ void __launch_bounds__(1024, 1) hashgrid3d_kernel(
    const float2* __restrict__ tables,
    float4* __restrict__ out,
    int n)
{
    const int DN[9]   = {16, 20, 25, 32, 40, 51, 64, 81, 102};   // levels 0..8
    const int DOFF[9] = {DOFF0, DOFF1, DOFF2, DOFF3, DOFF4, DOFF5, DOFF6, DOFF7, DOFF8};
    const int HN[7]   = {128, 161, 203, 256, 323, 406, 512};     // levels 9..15

    const int stride = gridDim.x * blockDim.x;
    for (int i = blockIdx.x * blockDim.x + threadIdx.x; i < n; i += stride) {
        const float4 q = __ldg(g_perm + i);   // coalesced; Morton-sorted
        const float x = q.x, y = q.y, z = q.z;
        const int p = __float_as_int(q.w);    // original point index

        float4* o = out + (size_t)p * 8;
        float4 r;

        // levels 0..8 dense (L1-resident hot sets under sorting)
        level_dense(g_dense + DOFF[0], DN[0], x, y, z, r.x, r.y);
        level_dense(g_dense + DOFF[1], DN[1], x, y, z, r.z, r.w);
        o[0] = r;
        level_dense(g_dense + DOFF[2], DN[2], x, y, z, r.x, r.y);
        level_dense(g_dense + DOFF[3], DN[3], x, y, z, r.z, r.w);
        o[1] = r;
        level_dense(g_dense + DOFF[4], DN[4], x, y, z, r.x, r.y);
        level_dense(g_dense + DOFF[5], DN[5], x, y, z, r.z, r.w);
        o[2] = r;
        level_dense(g_dense + DOFF[6], DN[6], x, y, z, r.x, r.y);
        level_dense(g_dense + DOFF[7], DN[7], x, y, z, r.z, r.w);
        o[3] = r;
        level_dense(g_dense + DOFF[8], DN[8], x, y, z, r.x, r.y);
        level_ldg(tables + (size_t)9 * T_SIZE, HN[0], x, y, z, r.z, r.w);
        o[4] = r;

        // levels 10..15 hashed -> o[5..7]
#pragma unroll
        for (int g = 0; g < 3; ++g) {
            const int l0 = 1 + 2 * g, l1 = 2 + 2 * g;  // indices into HN
            level_ldg(tables + (size_t)(l0 + 9) * T_SIZE, HN[l0], x, y, z, r.x, r.y);
            level_ldg(tables + (size_t)(l1 + 9) * T_SIZE, HN[l1], x, y, z, r.z, r.w);
            o[5 + g] = r;
        }
    }
}

extern "C" void kernel_launch(void* const* d_in, const int* in_sizes, int n_in,
                              void* d_out, int out_size)
{
    const float*  xyt    = (const float*)d_in[0];
    const float2* tables = (const float2*)d_in[1];
    float4*       out    = (float4*)d_out;

    const int n = in_sizes[0] / 3;    // 1048576 points

    // one-time host-side resources (no device memory involved)
    static bool init_done = false;
    static cudaStream_t s_build;
    static cudaEvent_t ev_fork, ev_join;
    if (!init_done) {
        cudaStreamCreateWithFlags(&s_build, cudaStreamNonBlocking);
        cudaEventCreateWithFlags(&ev_fork, cudaEventDisableTiming);
        cudaEventCreateWithFlags(&ev_join, cudaEventDisableTiming);
        init_done = true;
    }

    // fork: build_dense runs concurrently with the sort chain
    cudaEventRecord(ev_fork, 0);
    cudaStreamWaitEvent(s_build, ev_fork, 0);
    build_dense_kernel<<<(BPAIRS_TOTAL + 255) / 256, 256, 0, s_build>>>(tables);
    cudaEventRecord(ev_join, s_build);

    // sort chain on the main (captured) stream
    zero_kernel<<<(NBUCKETS + 255) / 256, 256>>>();
    hist_kernel<<<(n + 255) / 256, 256>>>(xyt, n);
    scan_kernel<<<1, 1024>>>();
    scatter_kernel<<<(n + 255) / 256, 256>>>(xyt, n);

    // join, then main kernel needs both g_perm and g_dense
    cudaStreamWaitEvent(0, ev_join, 0);
    hashgrid3d_kernel<<<148, 1024>>>(tables, out, n);
}

// round 11
// speedup vs baseline: 1.1102x; 1.1102x over previous
#include <cuda_runtime.h>
#include <cstdint>

// HashGrid3D: 16-level Instant-NGP style hash grid encode.
// xyt: (1048576, 3) fp32 in [0,1); tables: (16, 524288, 2) fp32.
// out: (1048576, 32) fp32.
//
// hash(c) = (cx*1 ^ cy*2654435761 ^ cz*805459861) & (T-1), T = 2^19.
//
// R11: profiler exposed scan_kernel at 37us (uncoalesced per-thread chunk
// loads, 1 SM, latency-bound). Rewrite: coalesced load into padded smem,
// per-thread reduce from smem (conflict-free via stride-33 padding),
// Hillis-Steele over thread sums, coalesced write-back. ~4us.
// Main kernel + rest of pipeline identical to R10 (zero smem -> full L1,
// dense gmem levels 0-8, hashed 9-15, Morton buckets, forked build).

#define T_SIZE 524288u
#define HMASK  (T_SIZE - 1u)
#define PY     2654435761u
#define PZ     805459861u

#define NPTS 1048576

// dense levels 0..8: N = 16,20,25,32,40,51,64,81,102
#define DENSE_TOTAL 2111933
__device__ float4 g_dense[DENSE_TOTAL];   // 33.8 MB scratch

#define DOFF0 0
#define DOFF1 4096
#define DOFF2 12096
#define DOFF3 27721
#define DOFF4 60489
#define DOFF5 124489
#define DOFF6 257140
#define DOFF7 519284
#define DOFF8 1050725

// build: one thread per x-PAIR of entries, pairs/level = ceil(N/2)*N*N
#define BPAIRS_TOTAL 1060860
#define BPA 0
#define BPB 2048
#define BPC 6048
#define BPD 14173
#define BPE 30557
#define BPF 62557
#define BPG 130183
#define BPH 261255
#define BPI 530256

// ---- spatial binning scratch ----
#define NBDIM 32
#define NBUCKETS (NBDIM * NBDIM * NBDIM)   // 32768
__device__ uint32_t g_count[NBUCKETS];     // counts -> exclusive bases (scan)
__device__ uint32_t g_rank[NPTS];          // per-point rank within bucket
__device__ float4   g_perm[NPTS];          // (x,y,z, bit-cast orig idx)

// padded smem for scan: index i lives at i + i/32 (stride-33 rows)
#define SCAN_SMEM_WORDS (NBUCKETS + NBUCKETS / 32)     // 33792
#define SCAN_SMEM_BYTES (SCAN_SMEM_WORDS * 4)          // 135168

struct Corners { float2 g[8]; };

__device__ __forceinline__ void trilerp(
    const Corners& c, float tx, float ty, float tz, float& r0, float& r1)
{
    const float ux = 1.0f - tx, uy = 1.0f - ty, uz = 1.0f - tz;
    const float wy0z0 = uy * uz, wy1z0 = ty * uz;
    const float wy0z1 = uy * tz, wy1z1 = ty * tz;
    const float w000 = ux * wy0z0, w100 = tx * wy0z0;
    const float w010 = ux * wy1z0, w110 = tx * wy1z0;
    const float w001 = ux * wy0z1, w101 = tx * wy0z1;
    const float w011 = ux * wy1z1, w111 = tx * wy1z1;

    float a = w000 * c.g[0].x;
    float b = w000 * c.g[0].y;
    a = fmaf(w100, c.g[1].x, a);  b = fmaf(w100, c.g[1].y, b);
    a = fmaf(w010, c.g[2].x, a);  b = fmaf(w010, c.g[2].y, b);
    a = fmaf(w110, c.g[3].x, a);  b = fmaf(w110, c.g[3].y, b);
    a = fmaf(w001, c.g[4].x, a);  b = fmaf(w001, c.g[4].y, b);
    a = fmaf(w101, c.g[5].x, a);  b = fmaf(w101, c.g[5].y, b);
    a = fmaf(w011, c.g[6].x, a);  b = fmaf(w011, c.g[6].y, b);
    a = fmaf(w111, c.g[7].x, a);  b = fmaf(w111, c.g[7].y, b);
    r0 = a; r1 = b;
}

__device__ __forceinline__ void corner_setup(
    int N, float x, float y, float z,
    int& ix, int& iy, int& iz, int& ix1, int& iy1, int& iz1,
    float& tx, float& ty, float& tz)
{
    const float fN = (float)N;
    float sx = x * fN, sy = y * fN, sz = z * fN;
    float fx = floorf(sx), fy = floorf(sy), fz = floorf(sz);
    tx = sx - fx; ty = sy - fy; tz = sz - fz;
    ix = (int)fx; iy = (int)fy; iz = (int)fz;
    if (ix >= N) ix -= N;
    if (iy >= N) iy -= N;
    if (iz >= N) iz -= N;
    ix1 = ix + 1; if (ix1 >= N) ix1 -= N;
    iy1 = iy + 1; if (iy1 >= N) iy1 -= N;
    iz1 = iz + 1; if (iz1 >= N) iz1 -= N;
}

// hashed LDG level with x-parity LDG.128 merging (levels 9..15)
__device__ __forceinline__ void level_ldg(
    const float2* __restrict__ tbl, int N,
    float x, float y, float z, float& r0, float& r1)
{
    int ix, iy, iz, ix1, iy1, iz1;
    float tx, ty, tz;
    corner_setup(N, x, y, z, ix, iy, iz, ix1, iy1, iz1, tx, ty, tz);

    const uint32_t hy0 = (uint32_t)iy  * PY, hy1 = (uint32_t)iy1 * PY;
    const uint32_t hz0 = (uint32_t)iz  * PZ, hz1 = (uint32_t)iz1 * PZ;
    const uint32_t ux0 = (uint32_t)ix,  ux1 = (uint32_t)ix1;
    uint32_t s[4];
    s[0] = hy0 ^ hz0; s[1] = hy1 ^ hz0; s[2] = hy0 ^ hz1; s[3] = hy1 ^ hz1;

    Corners c;
    const bool pair = ((ix & 1) == 0) && (ix1 == ix + 1);
    if (pair) {
        const float4* __restrict__ tbl4 = (const float4*)tbl;
#pragma unroll
        for (int k = 0; k < 4; ++k) {
            uint32_t h0 = (ux0 ^ s[k]) & HMASK;          // h1 = h0 ^ 1
            float4 q = __ldg(tbl4 + (h0 >> 1));
            if (h0 & 1) { c.g[2*k] = make_float2(q.z, q.w); c.g[2*k+1] = make_float2(q.x, q.y); }
            else        { c.g[2*k] = make_float2(q.x, q.y); c.g[2*k+1] = make_float2(q.z, q.w); }
        }
    } else {
#pragma unroll
        for (int k = 0; k < 4; ++k) {
            uint32_t h0 = (ux0 ^ s[k]) & HMASK;
            uint32_t h1 = (ux1 ^ s[k]) & HMASK;
            c.g[2*k]   = __ldg(tbl + h0);
            c.g[2*k+1] = __ldg(tbl + h1);
        }
    }
    trilerp(c, tx, ty, tz, r0, r1);
}

// dense gmem level: x-pair + x-wrap baked into float4 entries (levels 0..8)
__device__ __forceinline__ void level_dense(
    const float4* __restrict__ t4, int N,
    float x, float y, float z, float& r0, float& r1)
{
    int ix, iy, iz, ix1, iy1, iz1;
    float tx, ty, tz;
    corner_setup(N, x, y, z, ix, iy, iz, ix1, iy1, iz1, tx, ty, tz);

    const int NN = N * N;
    const float4 q00 = __ldg(t4 + iz  * NN + iy  * N + ix);
    const float4 q10 = __ldg(t4 + iz  * NN + iy1 * N + ix);
    const float4 q01 = __ldg(t4 + iz1 * NN + iy  * N + ix);
    const float4 q11 = __ldg(t4 + iz1 * NN + iy1 * N + ix);

    Corners c;
    c.g[0] = make_float2(q00.x, q00.y); c.g[1] = make_float2(q00.z, q00.w);
    c.g[2] = make_float2(q10.x, q10.y); c.g[3] = make_float2(q10.z, q10.w);
    c.g[4] = make_float2(q01.x, q01.y); c.g[5] = make_float2(q01.z, q01.w);
    c.g[6] = make_float2(q11.x, q11.y); c.g[7] = make_float2(q11.z, q11.w);
    trilerp(c, tx, ty, tz, r0, r1);
}

// ---- binning pipeline ----

// spread 5 bits to every 3rd position (for 15-bit Morton)
__device__ __forceinline__ uint32_t spread5(uint32_t x)
{
    x &= 0x1Fu;
    x = (x | (x << 8)) & 0x100Fu;
    x = (x | (x << 4)) & 0x10C3u;
    x = (x | (x << 2)) & 0x1249u;
    return x;
}

__device__ __forceinline__ int bucket_of(float x, float y, float z)
{
    int bx = (int)(x * (float)NBDIM); if (bx > NBDIM - 1) bx = NBDIM - 1;
    int by = (int)(y * (float)NBDIM); if (by > NBDIM - 1) by = NBDIM - 1;
    int bz = (int)(z * (float)NBDIM); if (bz > NBDIM - 1) bz = NBDIM - 1;
    // Morton order: consecutive buckets form compact 3D blocks
    return (int)(spread5((uint32_t)bx) | (spread5((uint32_t)by) << 1)
                 | (spread5((uint32_t)bz) << 2));
}

__global__ void __launch_bounds__(256) zero_kernel()
{
    const int i = blockIdx.x * blockDim.x + threadIdx.x;
    if (i < NBUCKETS) g_count[i] = 0;
}

__global__ void __launch_bounds__(256) hist_kernel(const float* __restrict__ xyt, int n)
{
    const int p = blockIdx.x * blockDim.x + threadIdx.x;
    if (p >= n) return;
    const float x = xyt[3 * p + 0];
    const float y = xyt[3 * p + 1];
    const float z = xyt[3 * p + 2];
    g_rank[p] = atomicAdd(&g_count[bucket_of(x, y, z)], 1u);
}

// single-block exclusive scan, coalesced through padded smem.
// element i lives at smem index i + i/32; thread t owns elements
// t*32..t*32+31 -> padded t*33..t*33+31 (bank (t+j)%32: conflict-free).
__global__ void __launch_bounds__(1024) scan_kernel()
{
    extern __shared__ uint32_t sh[];          // SCAN_SMEM_WORDS
    __shared__ uint32_t tsum[1024];
    const int t = threadIdx.x;

    for (int j = t; j < NBUCKETS; j += 1024)  // coalesced gmem read
        sh[j + (j >> 5)] = g_count[j];
    __syncthreads();

    const int base = t * 33;
    uint32_t vals[32];
    uint32_t s = 0;
#pragma unroll
    for (int j = 0; j < 32; ++j) { vals[j] = sh[base + j]; s += vals[j]; }
    tsum[t] = s;
    __syncthreads();

    for (int off = 1; off < 1024; off <<= 1) {
        uint32_t v = (t >= off) ? tsum[t - off] : 0u;
        __syncthreads();
        tsum[t] += v;
        __syncthreads();
    }

    uint32_t run = (t == 0) ? 0u : tsum[t - 1];   // exclusive prefix
#pragma unroll
    for (int j = 0; j < 32; ++j) { uint32_t c = vals[j]; sh[base + j] = run; run += c; }
    __syncthreads();

    for (int j = t; j < NBUCKETS; j += 1024)  // coalesced gmem write
        g_count[j] = sh[j + (j >> 5)];
}

// atomic-free scatter: slot = base[bucket] + rank[p]
__global__ void __launch_bounds__(256) scatter_kernel(const float* __restrict__ xyt, int n)
{
    const int p = blockIdx.x * blockDim.x + threadIdx.x;
    if (p >= n) return;
    const float x = xyt[3 * p + 0];
    const float y = xyt[3 * p + 1];
    const float z = xyt[3 * p + 2];
    const uint32_t slot = g_count[bucket_of(x, y, z)] + g_rank[p];
    g_perm[slot] = make_float4(x, y, z, __int_as_float(p));
}

// ---- pre-kernel: materialize dense x-paired tables for levels 0..8 ----
__global__ void __launch_bounds__(256) build_dense_kernel(
    const float2* __restrict__ tables)
{
    const int i = blockIdx.x * blockDim.x + threadIdx.x;
    if (i >= BPAIRS_TOTAL) return;

    const int POFF[9]  = {BPA, BPB, BPC, BPD, BPE, BPF, BPG, BPH, BPI};
    const int DOFF[9]  = {DOFF0, DOFF1, DOFF2, DOFF3, DOFF4, DOFF5, DOFF6, DOFF7, DOFF8};
    const int DN[9]    = {16, 20, 25, 32, 40, 51, 64, 81, 102};

    int l = 0;
#pragma unroll
    for (int k = 1; k < 9; ++k) if (i >= POFF[k]) l = k;

    const int N = DN[l];
    const int hw = (N + 1) >> 1;        // pairs per row
    const int local = i - POFF[l];
    const int pi = local % hw;
    const int r  = local / hw;
    const int iy = r % N;
    const int iz = r / N;
    const int ix = 2 * pi;

    const float2* __restrict__ tbl  = tables + (size_t)l * T_SIZE;
    const float4* __restrict__ tbl4 = (const float4*)tbl;
    const uint32_t s = ((uint32_t)iy * PY) ^ ((uint32_t)iz * PZ);

    const uint32_t h0 = ((uint32_t)ix ^ s) & HMASK;
    const float4 q = __ldg(tbl4 + (h0 >> 1));
    float2 ga, gb;   // g(ix), g(ix+1)
    if (h0 & 1) { ga = make_float2(q.z, q.w); gb = make_float2(q.x, q.y); }
    else        { ga = make_float2(q.x, q.y); gb = make_float2(q.z, q.w); }

    const int x2 = (ix + 2 < N) ? ix + 2 : ix + 2 - N;
    const float2 gc = __ldg(tbl + (((uint32_t)x2 ^ s) & HMASK));

    float4* dst = g_dense + DOFF[l] + (size_t)(iz * N + iy) * N + ix;
    if (ix + 1 < N) {
        dst[0] = make_float4(ga.x, ga.y, gb.x, gb.y);
        dst[1] = make_float4(gb.x, gb.y, gc.x, gc.y);
    } else {
        // even N never hits this; odd N last lone entry: (g(N-1), g(0))
        const float2 g0 = __ldg(tbl + (s & HMASK));     // x=0 -> h = s
        dst[0] = make_float4(ga.x, ga.y, g0.x, g0.y);
    }
}

__global__ void __launch_bounds__(1024, 1) hashgrid3d_kernel(
    const float2* __restrict__ tables,
    float4* __restrict__ out,
    int n)
{
    const int DN[9]   = {16, 20, 25, 32, 40, 51, 64, 81, 102};   // levels 0..8
    const int DOFF[9] = {DOFF0, DOFF1, DOFF2, DOFF3, DOFF4, DOFF5, DOFF6, DOFF7, DOFF8};
    const int HN[7]   = {128, 161, 203, 256, 323, 406, 512};     // levels 9..15

    const int stride = gridDim.x * blockDim.x;
    for (int i = blockIdx.x * blockDim.x + threadIdx.x; i < n; i += stride) {
        const float4 q = __ldg(g_perm + i);   // coalesced; Morton-sorted
        const float x = q.x, y = q.y, z = q.z;
        const int p = __float_as_int(q.w);    // original point index

        float4* o = out + (size_t)p * 8;
        float4 r;

        // levels 0..8 dense (L1-resident hot sets under sorting)
        level_dense(g_dense + DOFF[0], DN[0], x, y, z, r.x, r.y);
        level_dense(g_dense + DOFF[1], DN[1], x, y, z, r.z, r.w);
        o[0] = r;
        level_dense(g_dense + DOFF[2], DN[2], x, y, z, r.x, r.y);
        level_dense(g_dense + DOFF[3], DN[3], x, y, z, r.z, r.w);
        o[1] = r;
        level_dense(g_dense + DOFF[4], DN[4], x, y, z, r.x, r.y);
        level_dense(g_dense + DOFF[5], DN[5], x, y, z, r.z, r.w);
        o[2] = r;
        level_dense(g_dense + DOFF[6], DN[6], x, y, z, r.x, r.y);
        level_dense(g_dense + DOFF[7], DN[7], x, y, z, r.z, r.w);
        o[3] = r;
        level_dense(g_dense + DOFF[8], DN[8], x, y, z, r.x, r.y);
        level_ldg(tables + (size_t)9 * T_SIZE, HN[0], x, y, z, r.z, r.w);
        o[4] = r;

        // levels 10..15 hashed -> o[5..7]
#pragma unroll
        for (int g = 0; g < 3; ++g) {
            const int l0 = 1 + 2 * g, l1 = 2 + 2 * g;  // indices into HN
            level_ldg(tables + (size_t)(l0 + 9) * T_SIZE, HN[l0], x, y, z, r.x, r.y);
            level_ldg(tables + (size_t)(l1 + 9) * T_SIZE, HN[l1], x, y, z, r.z, r.w);
            o[5 + g] = r;
        }
    }
}

extern "C" void kernel_launch(void* const* d_in, const int* in_sizes, int n_in,
                              void* d_out, int out_size)
{
    const float*  xyt    = (const float*)d_in[0];
    const float2* tables = (const float2*)d_in[1];
    float4*       out    = (float4*)d_out;

    const int n = in_sizes[0] / 3;    // 1048576 points

    // one-time host-side resources (no device memory involved)
    static bool init_done = false;
    static cudaStream_t s_build;
    static cudaEvent_t ev_fork, ev_join;
    if (!init_done) {
        cudaStreamCreateWithFlags(&s_build, cudaStreamNonBlocking);
        cudaEventCreateWithFlags(&ev_fork, cudaEventDisableTiming);
        cudaEventCreateWithFlags(&ev_join, cudaEventDisableTiming);
        cudaFuncSetAttribute(scan_kernel,
                             cudaFuncAttributeMaxDynamicSharedMemorySize,
                             SCAN_SMEM_BYTES);
        init_done = true;
    }

    // fork: build_dense runs concurrently with the sort chain
    cudaEventRecord(ev_fork, 0);
    cudaStreamWaitEvent(s_build, ev_fork, 0);
    build_dense_kernel<<<(BPAIRS_TOTAL + 255) / 256, 256, 0, s_build>>>(tables);
    cudaEventRecord(ev_join, s_build);

    // sort chain on the main (captured) stream
    zero_kernel<<<(NBUCKETS + 255) / 256, 256>>>();
    hist_kernel<<<(n + 255) / 256, 256>>>(xyt, n);
    scan_kernel<<<1, 1024, SCAN_SMEM_BYTES>>>();
    scatter_kernel<<<(n + 255) / 256, 256>>>(xyt, n);

    // join, then main kernel needs both g_perm and g_dense
    cudaStreamWaitEvent(0, ev_join, 0);
    hashgrid3d_kernel<<<148, 1024>>>(tables, out, n);
}